// round 15
// baseline (speedup 1.0000x reference)
#include <cuda_runtime.h>
#include <stdint.h>

#define H    768
#define NN   32
#define KK   32
#define TT   128
#define NEGINF -1e20f

#define GRID 132
#define THREADS 512

// ---- output layout (concatenated, float32) ----
#define OFF_SCORE 0
#define OFF_ENC   1024
#define OFF_MASK  3146752
#define OFF_USE   3150848
#define OFF_IDX   3175424

// ---- gather partition (float4 units, total 786432) ----
#define ENC_F4 786432
#define RA_LO 0
#define RA_HI 262144
#define RB_LO 262144
#define RB_HI 524288
#define RC_LO 524288
#define RC_HI ENC_F4

// ---- v-GEMV split ----
#define GSPLIT 32
#define GCH    24                 // g per split (32*24 = 768)

// ---- scratch ----
__device__ float g_cqkT[H * NN];          // transposed: [g][n]
__device__ float g_vpart[GSPLIT][NN * H]; // [split][n*768+h]
__device__ float g_c[NN];
__device__ unsigned int g_count = 0;
__device__ unsigned int g_sense = 0;

__device__ __forceinline__ void grid_barrier(unsigned int& local_sense) {
    __syncthreads();
    if (threadIdx.x == 0) {
        unsigned int next = local_sense ^ 1u;
        __threadfence();
        unsigned int old = atomicAdd(&g_count, 1u);
        if (old == GRID - 1) {
            atomicExch(&g_count, 0u);
            __threadfence();
            atomicExch(&g_sense, next);
        } else {
            while (*((volatile unsigned int*)&g_sense) != next) { }
        }
    }
    local_sense ^= 1u;
    __syncthreads();
}

// 4-way unrolled gather of float4 range [lo,hi)
__device__ __forceinline__ void gather_range(const float4* __restrict__ p0,
                                             const int* __restrict__ label,
                                             float4* __restrict__ outE,
                                             int lo, int hi,
                                             int my, int nthr) {
    int i = lo + my;
    for (; i + 3 * nthr < hi; i += 4 * nthr) {
        int i0 = i, i1 = i + nthr, i2 = i + 2 * nthr, i3 = i + 3 * nthr;
        int n0 = i0 / 24576, n1 = i1 / 24576, n2 = i2 / 24576, n3 = i3 / 24576;
        float4 v0 = p0[(size_t)(n0 * KK + label[n0]) * 24576 + (i0 - n0 * 24576)];
        float4 v1 = p0[(size_t)(n1 * KK + label[n1]) * 24576 + (i1 - n1 * 24576)];
        float4 v2 = p0[(size_t)(n2 * KK + label[n2]) * 24576 + (i2 - n2 * 24576)];
        float4 v3 = p0[(size_t)(n3 * KK + label[n3]) * 24576 + (i3 - n3 * 24576)];
        outE[i0] = v0; outE[i1] = v1; outE[i2] = v2; outE[i3] = v3;
    }
    for (; i < hi; i += nthr) {
        int n = i / 24576;
        outE[i] = p0[(size_t)(n * KK + label[n]) * 24576 + (i - n * 24576)];
    }
}

__global__ __launch_bounds__(THREADS, 1)
void fused_kernel(const float* __restrict__ ctx,
                  const float* __restrict__ tracked,
                  const float* __restrict__ pool0,
                  const float* __restrict__ pool1,
                  const int*   __restrict__ pmask,
                  const int*   __restrict__ ckmask,
                  const int*   __restrict__ label,
                  const int*   __restrict__ ptok,
                  const float* __restrict__ Wcqk,
                  const float* __restrict__ bcqk,
                  const float* __restrict__ Wk,
                  const float* __restrict__ bk,
                  float* __restrict__ out) {
    // 36 KB shared, reused per phase
    __shared__ __align__(16) float smem_u[9216];

    const int b    = blockIdx.x;
    const int tid  = threadIdx.x;
    const int lane = tid & 31;
    const int wid  = tid >> 5;

    unsigned int local_sense = *((volatile unsigned int*)&g_sense);

    const float4* p0f4  = (const float4*)pool0;
    float4*       outE4 = (float4*)(out + OFF_ENC);

    // ===================== PHASE A =====================
    // blocks 0..95: cqk_proT[h][n]  (warp = (h-pair, j-quarter), 2 h reuse)
    // blocks 96..131: gather RA
    if (b < 96) {
        float* s   = smem_u;                  // [32][256]
        float* red = smem_u + 8192;           // [4 pl][4 jq][2 ab][32 n]
        const int pl = wid >> 2;              // 0..3
        const int jq = wid & 3;               // 0..3
        const int h_a = b * 4 + pl;           // 0..383
        const int h_b = h_a + 384;            // 384..767
        const float* wra = Wcqk + (size_t)h_a * (2 * H);
        const float* wrb = Wcqk + (size_t)h_b * (2 * H);

        float acc_a[NN], acc_b[NN];
#pragma unroll
        for (int n = 0; n < NN; n++) { acc_a[n] = 0.f; acc_b[n] = 0.f; }

        for (int c = 0; c < 6; c++) {
            if (c) __syncthreads();
            for (int idx = tid; idx < NN * 256; idx += THREADS) {
                int n  = idx >> 8;
                int jj = idx & 255;
                int j  = c * 256 + jj;
                s[idx] = (j < H) ? ctx[n * 3 * H + 2 * H + j]
                                 : tracked[n * H + (j - H)];
            }
            __syncthreads();
#pragma unroll
            for (int r = 0; r < 2; r++) {
                int jj = jq * 64 + r * 32 + lane;
                int j  = c * 256 + jj;
                float w_a = wra[j];
                float w_b = wrb[j];
#pragma unroll
                for (int n = 0; n < NN; n++) {
                    float sv = s[n * 256 + jj];
                    acc_a[n] += w_a * sv;
                    acc_b[n] += w_b * sv;
                }
            }
        }
        // lane-reduce each n; lane==n keeps the value
#pragma unroll
        for (int n = 0; n < NN; n++) {
            float va = acc_a[n], vb = acc_b[n];
#pragma unroll
            for (int o = 16; o > 0; o >>= 1) {
                va += __shfl_xor_sync(0xffffffffu, va, o);
                vb += __shfl_xor_sync(0xffffffffu, vb, o);
            }
            if (lane == n) {
                red[((pl * 4 + jq) * 2 + 0) * 32 + n] = va;
                red[((pl * 4 + jq) * 2 + 1) * 32 + n] = vb;
            }
        }
        __syncthreads();
        if (wid < 4) {
            const int p2 = wid;
            const int ha = b * 4 + p2, hb = ha + 384;
            float sa = 0.f, sb = 0.f;
#pragma unroll
            for (int q = 0; q < 4; q++) {
                sa += red[((p2 * 4 + q) * 2 + 0) * 32 + lane];
                sb += red[((p2 * 4 + q) * 2 + 1) * 32 + lane];
            }
            g_cqkT[ha * NN + lane] = sa + bcqk[ha];
            g_cqkT[hb * NN + lane] = sb + bcqk[hb];
        }
    } else {
        gather_range(p0f4, label, outE4, RA_LO, RA_HI,
                     (b - 96) * THREADS + tid, 36 * THREADS);
    }

    grid_barrier(local_sense);

    // ===================== PHASE B =====================
    // blocks 0..47: v partials  (thread = (h, gsplit), float4 smem reads)
    // block 48:     c[n] = bk . cqk_pro[n]
    // blocks 49..131: small outputs + gather RB
    if (b < 48) {
        float* cs = smem_u;                   // [48][32] staged cqkT rows
        const int global = b * THREADS + tid; // < 24576
        const int gc     = global / H;        // 0..31
        const int h      = global - gc * H;
        const int gc_lo  = (b * THREADS) / H;
        // stage rows [gc_lo*24, gc_lo*24+48)
        for (int idx = tid; idx < 48 * NN; idx += THREADS) {
            int gl = idx >> 5;
            int n  = idx & 31;
            int gg = gc_lo * GCH + gl;
            cs[gl * NN + n] = (gg < H) ? g_cqkT[gg * NN + n] : 0.f;
        }
        __syncthreads();

        const int soff = (gc - gc_lo) * GCH;
        float acc[NN];
#pragma unroll
        for (int n = 0; n < NN; n++) acc[n] = 0.f;
#pragma unroll 4
        for (int g = 0; g < GCH; g++) {
            float w = Wk[(size_t)(gc * GCH + g) * H + h];
            const float* crow = cs + (soff + g) * NN;
#pragma unroll
            for (int n4 = 0; n4 < 8; n4++) {
                float4 c4 = *(const float4*)(crow + n4 * 4);
                acc[n4 * 4 + 0] += c4.x * w;
                acc[n4 * 4 + 1] += c4.y * w;
                acc[n4 * 4 + 2] += c4.z * w;
                acc[n4 * 4 + 3] += c4.w * w;
            }
        }
#pragma unroll
        for (int n = 0; n < NN; n++) g_vpart[gc][n * H + h] = acc[n];
    } else if (b == 48) {
#pragma unroll
        for (int rep = 0; rep < 2; rep++) {
            int n = wid * 2 + rep;            // 0..31
            float a = 0.f;
            for (int g = lane; g < H; g += 32) a += bk[g] * g_cqkT[g * NN + n];
#pragma unroll
            for (int o = 16; o > 0; o >>= 1) a += __shfl_xor_sync(0xffffffffu, a, o);
            if (lane == 0) g_c[n] = a;
        }
    } else {
        int my = (b - 49) * THREADS + tid;    // < 42496
        // small outputs (33792 elements), no phase dependency
        if (my < 4096) {
            int n = my >> 7, t = my & 127;
            out[OFF_MASK + my] =
                (pmask[(n * KK + label[n]) * TT + t] != 0) ? 1.f : 0.f;
        } else if (my < 4096 + 24576) {
            int j = my - 4096;
            int n = j / H, h2 = j - n * H;
            out[OFF_USE + j] = pool1[(size_t)(n * KK + label[n]) * H + h2];
        } else if (my < 4096 + 24576 + 4096) {
            int j = my - 4096 - 24576;
            int n = j >> 7, t = j & 127;
            out[OFF_IDX + j] = (float)ptok[(n * KK + label[n]) * TT + t];
        }
        gather_range(p0f4, label, outE4, RB_LO, RB_HI, my, 83 * THREADS);
    }

    grid_barrier(local_sense);

    // ===================== PHASE C =====================
    // blocks 0..63: score (block = (n, k-half); inline v reduction into smem)
    // blocks 64..131: gather RC
    if (b < 64) {
        float* sv = smem_u;                   // [768] v[n]
        const int n = b >> 1;
        for (int h = tid; h < H; h += THREADS) {
            float s0 = 0.f, s1 = 0.f, s2 = 0.f, s3 = 0.f;
#pragma unroll
            for (int p = 0; p < 8; p++) {
                s0 += g_vpart[4 * p + 0][n * H + h];
                s1 += g_vpart[4 * p + 1][n * H + h];
                s2 += g_vpart[4 * p + 2][n * H + h];
                s3 += g_vpart[4 * p + 3][n * H + h];
            }
            sv[h] = (s0 + s1) + (s2 + s3);
        }
        __syncthreads();

        const int k = (b & 1) * 16 + wid;     // 0..31
        const float4* p4 = (const float4*)(pool1 + (size_t)(n * KK + k) * H);
        const float4* v4 = (const float4*)sv;
        float a = 0.f;
#pragma unroll
        for (int i = 0; i < 6; i++) {
            float4 p = p4[lane + 32 * i];
            float4 v = v4[lane + 32 * i];
            a += p.x * v.x + p.y * v.y + p.z * v.z + p.w * v.w;
        }
#pragma unroll
        for (int o = 16; o > 0; o >>= 1) a += __shfl_xor_sync(0xffffffffu, a, o);
        if (lane == 0)
            out[OFF_SCORE + n * KK + k] =
                (ckmask[n * KK + k] != 0) ? (a + g_c[n]) : NEGINF;
    } else {
        gather_range(p0f4, label, outE4, RC_LO, RC_HI,
                     (b - 64) * THREADS + tid, 68 * THREADS);
    }
}

extern "C" void kernel_launch(void* const* d_in, const int* in_sizes, int n_in,
                              void* d_out, int out_size) {
    const float* ctx     = (const float*)d_in[0];   // (32,3,768)
    const float* tracked = (const float*)d_in[1];   // (32,768)
    const float* pool0   = (const float*)d_in[2];   // (32,32,128,768)
    const float* pool1   = (const float*)d_in[3];   // (32,32,768)
    const int*   pmask   = (const int*)d_in[4];     // (32,32,128) bool->4B
    const int*   ckmask  = (const int*)d_in[5];     // (32,32)     bool->4B
    const int*   label   = (const int*)d_in[6];     // (32,)
    const int*   ptok    = (const int*)d_in[7];     // (32,32,128)
    const float* Wcqk    = (const float*)d_in[8];   // (768,1536)
    const float* bcqk    = (const float*)d_in[9];   // (768,)
    const float* Wk      = (const float*)d_in[10];  // (768,768)
    const float* bk      = (const float*)d_in[11];  // (768,)
    float* out = (float*)d_out;

    fused_kernel<<<GRID, THREADS>>>(ctx, tracked, pool0, pool1, pmask, ckmask,
                                    label, ptok, Wcqk, bcqk, Wk, bk, out);
}